// round 16
// baseline (speedup 1.0000x reference)
#include <cuda_runtime.h>
#include <cstdint>
#include <math.h>

// SoftPolygon B=32, P=32, 128x128.  out[b,y,x] = sigmoid(min_seg_sq * io)
//
// v16: v15 skeleton (2048 x 128thr, warp = half-row, compacted edge list,
//      fast div, tanh-approx sigmoid, float2 stores) +
//  - CULL_T = 6.25 (2.5px band): culled-pixel L2-rel error ~1e-4 (model:
//    perim/(2 sqrt(T)) * e^(-2T)), 9x under the 1e-3 gate.
//  - cull dedup: tB dot = tA dot + 63*A; ga reuses xsA/xsB.
//  - inv (MUFU.RCP) hoisted ahead of the xint chain for MUFU overlap.

namespace {

constexpr int NB  = 32;
constexpr int NP  = 32;
constexpr int NH  = 128;
constexpr int NW  = 128;
constexpr int RPB = 2;             // rows per block (2 warps per row)
constexpr float CULL_T = 6.25f;    // sq-distance saturation threshold (2.5px)

__device__ __forceinline__ float sigmoid_fast(float v) {
    float t;
    asm("tanh.approx.f32 %0, %1;" : "=f"(t) : "f"(0.5f * v));
    return fmaf(0.5f, t, 0.5f);
}

__global__ __launch_bounds__(128) void soft_poly_kernel(
    const float* __restrict__ verts,   // (B, P, 2)
    float* __restrict__ out)           // (B, H, W)
{
    const int b    = blockIdx.y;
    const int row0 = blockIdx.x * RPB;
    const int tid  = threadIdx.x;
    const int w    = tid >> 5;         // warp 0..3
    const int lane = tid & 31;
    const int r    = w >> 1;           // local row 0..1
    const int hp   = w & 1;            // column half 0..1
    const int row  = row0 + r;
    const float gy = (float)row;

    __shared__ float  vbuf[NP * 2];    // interleaved x,y
    __shared__ float4 sA[4][NP];       // per-warp compacted {x1, A, c0, dx}
    __shared__ float2 sB[4][NP];       // per-warp compacted {dy, ys1}

    if (tid < NP * 2) vbuf[tid] = verts[(size_t)b * NP * 2 + tid];
    __syncthreads();

    // ---- per-(row, edge) precompute; edge = lane; warp-local ----
    const unsigned full = 0xffffffffu;
    const float sxa = (float)(hp * 64);
    const float sxb = sxa + 63.0f;
    unsigned int pmA, pmB;   // parity words for this warp's 2 column groups
    int nkeep;               // surviving edge count (warp-uniform)
    {
        const int i  = lane;
        const int jp = (i + NP - 1) & (NP - 1);   // prev vertex (roll +1)
        const int kn = (i + 1) & (NP - 1);        // next vertex (roll -1)
        const float fx = vbuf[2 * i],  fy = vbuf[2 * i + 1];
        const float tx = vbuf[2 * jp], ty = vbuf[2 * jp + 1];
        const float x2 = vbuf[2 * kn], y2 = vbuf[2 * kn + 1];

        // distance-edge constants first (MUFU.RCP overlaps the div below)
        const float dx = x2 - fx, dy = y2 - fy;
        const float sq  = dx * dx + dy * dy + 1e-5f;
        const float inv = __fdividef(1.0f, sq);   // continuous path
        const float ys1 = gy - fy;
        const float A   = dx * inv;

        // crossing threshold (fast div; flip-safety: the crossing point lies
        // ON the edge, so an affected pixel is within div_err of the
        // boundary -> both outputs ~0.5, per-flip error ~ err^2)
        const bool cond = (fy > gy) != (ty > gy);
        float xint = __fdividef((tx - fx) * (gy - fy), ty - fy) + fx;
        // crossing of parity-edge (jp->i) within THIS warp's span:
        // that edge is the distance edge of lane jp; shared via shfl below.
        const bool crossFlag = cond && (xint >= sxa) && (xint <= sxb);
        if (!cond) xint = -1.0f;
        // #columns c in [0,128) with (float)c < xint
        const float xc = fminf(fmaxf(ceilf(xint), 0.0f), 128.0f);
        const int ci = (int)xc - hp * 64;   // relative to this warp's half

        const int nA = min(max(ci,      0), 32);
        const int nB = min(max(ci - 32, 0), 32);
        const unsigned int mA = (unsigned int)((1ull << nA) - 1ull);
        const unsigned int mB = (unsigned int)((1ull << nB) - 1ull);
        pmA = __reduce_xor_sync(full, mA);
        pmB = __reduce_xor_sync(full, mB);

        // ---- EXACT cull: dist(span segment, edge segment)^2 <= CULL_T ----
        const float xsA = sxa - fx;
        const float xsB = sxb - fx;
        // (1) edge endpoint v_i -> span; v_{i+1}'s value = next lane's dva
        const float ga  = fmaxf(fmaxf(xsA, -xsB), 0.0f);
        const float dva = fmaf(ga, ga, ys1 * ys1);
        const float dvb = __shfl_sync(full, dva, (lane + 1) & 31);
        // (2) span endpoints -> edge; dot products differ by 63*A
        const float dtA = (xsA * dx + ys1 * dy) * inv;
        const float tA  = __saturatef(dtA);
        const float xpA = fmaf(-tA, dx, xsA);
        const float ypA = fmaf(-tA, dy, ys1);
        const float dpa = fmaf(xpA, xpA, ypA * ypA);
        const float tB  = __saturatef(fmaf(63.0f, A, dtA));
        const float xpB = fmaf(-tB, dx, xsB);
        const float ypB = fmaf(-tB, dy, ys1);
        const float dpb = fmaf(xpB, xpB, ypB * ypB);
        // (3) intersection: crossFlag of lane (i+1) is for edge (i -> i+1)
        const bool isect =
            (bool)__shfl_sync(full, (int)crossFlag, (lane + 1) & 31);

        const float best = fminf(fminf(dva, dvb), fminf(dpa, dpb));
        const bool keep = isect || (best <= CULL_T);
        const unsigned int kmask = __ballot_sync(full, keep);
        nkeep = __popc(kmask);

        if (keep) {   // compacted scatter: kept lane -> dense slot
            const int pos = __popc(kmask & ((1u << lane) - 1u));
            sA[w][pos] = make_float4(fx, A, ys1 * dy * inv, dx);
            sB[w][pos] = make_float2(dy, ys1);
        }
    }
    __syncwarp();   // sA/sB written and read by the same warp

    // ---- mainloop: compacted edges, adjacent-column pixel pair per lane ----
    const float gx0 = sxa + (float)(2 * lane);
    const float gx1 = gx0 + 1.0f;
    float mn0 = 3.402823466e38f, mn1 = mn0;

#define PIX(A_, B_, GX, MN) do {                               \
        const float xs  = (GX) - (A_).x;                       \
        const float dot = fmaf(xs, (A_).y, (A_).z);            \
        const float t   = __saturatef(dot);                    \
        const float xp  = fmaf(-t, (A_).w, xs);                \
        const float yp  = fmaf(-t, (B_).x, (B_).y);            \
        const float d   = fmaf(xp, xp, yp * yp);               \
        (MN) = fminf((MN), d);                                 \
    } while (0)

    int i = 0;
    for (; i + 2 <= nkeep; i += 2) {
        const float4 a0 = sA[w][i],     a1 = sA[w][i + 1];
        const float2 b0 = sB[w][i],     b1 = sB[w][i + 1];
        PIX(a0, b0, gx0, mn0);
        PIX(a0, b0, gx1, mn1);
        PIX(a1, b1, gx0, mn0);
        PIX(a1, b1, gx1, mn1);
    }
    if (i < nkeep) {
        const float4 a0 = sA[w][i];
        const float2 b0 = sB[w][i];
        PIX(a0, b0, gx0, mn0);
        PIX(a0, b0, gx1, mn1);
    }
#undef PIX

    // ---- epilogue: parity pair from 64-bit concat, fast sigmoid, STG.64 ----
    const unsigned long long p64 =
        (unsigned long long)pmA | ((unsigned long long)pmB << 32);
    const unsigned int pair = (unsigned int)(p64 >> (2 * lane)) & 3u;
    const float io0 = (pair & 1u) ? 1.0f : -1.0f;
    const float io1 = (pair & 2u) ? 1.0f : -1.0f;

    float2* op = (float2*)(out + ((size_t)b * NH + row) * NW + hp * 64) + lane;
    *op = make_float2(sigmoid_fast(mn0 * io0), sigmoid_fast(mn1 * io1));
}

}  // namespace

extern "C" void kernel_launch(void* const* d_in, const int* in_sizes, int n_in,
                              void* d_out, int out_size) {
    const float* verts = (const float*)d_in[0];
    float* out = (float*)d_out;
    dim3 grid(NH / RPB, NB);   // 64 x 32 = 2048 blocks, 128 threads each
    soft_poly_kernel<<<grid, 128>>>(verts, out);
}